// round 3
// baseline (speedup 1.0000x reference)
#include <cuda_runtime.h>
#include <cuda_bf16.h>
#include <math.h>
#include <stdint.h>

// Sigma_out[b][i][l] = p_i * p_l * ( S[i][l] - q[i] - r[l] + s )
//   p = softmax(mu[b]) ; q = S p ; r = p^T S ; s = p^T S p
// One CTA per batch row. Sigma staged once into smem with a per-row XOR
// swizzle so the row-dot (q), col-dot (r) and output passes are all
// bank-conflict free. ALL memory accesses are scalar 32-bit (no float4)
// to rule out any misaligned-address fault class.

#define C 128
#define THREADS 256
#define ELEMS_PER_THREAD (C * C / THREADS)   // 64

__global__ __launch_bounds__(THREADS) void softmax_sigma_kernel(
    const float* __restrict__ mu,       // [B, C]
    const float* __restrict__ Sigma,    // [B, C, C]
    float* __restrict__ mu_out,         // [B, C]
    float* __restrict__ sig_out)        // [B, C, C]
{
    const int b = blockIdx.x;
    const int t = threadIdx.x;

    extern __shared__ float sm[];
    float* Ssm = sm;              // C*C floats; row i, col k stored at [i*C + (k ^ (i&31))]
    float* p   = sm + C * C;      // 128
    float* qv  = p + C;           // 128
    float* rv  = qv + C;          // 128
    float* red = rv + C;          // 16 scratch

    const float* Sb = Sigma + (size_t)b * (C * C);
    float*       Ob = sig_out + (size_t)b * (C * C);

    // ---- softmax part 1: warp max of mu[b] (threads 0..127 own one class)
    float x = (t < C) ? mu[b * C + t] : -INFINITY;
    float v = x;
    #pragma unroll
    for (int o = 16; o > 0; o >>= 1)
        v = fmaxf(v, __shfl_xor_sync(0xffffffffu, v, o));
    if (t < C && (t & 31) == 0) red[t >> 5] = v;

    // ---- stage Sigma[b] -> smem, scalar coalesced loads, swizzled stores.
    // el = t + THREADS*j : per warp, one row, 32 consecutive cols -> both the
    // LDG (coalesced 128B) and the STS (xor-permuted 32 banks) are optimal.
    #pragma unroll
    for (int j = 0; j < ELEMS_PER_THREAD; ++j) {
        int el = t + THREADS * j;
        int i  = el >> 7;            // row
        int k  = el & (C - 1);       // col
        Ssm[i * C + (k ^ (i & 31))] = Sb[el];
    }

    __syncthreads();
    float m = fmaxf(fmaxf(red[0], red[1]), fmaxf(red[2], red[3]));
    float e = (t < C) ? expf(x - m) : 0.0f;
    v = e;
    #pragma unroll
    for (int o = 16; o > 0; o >>= 1)
        v += __shfl_xor_sync(0xffffffffu, v, o);
    if (t < C && (t & 31) == 0) red[8 + (t >> 5)] = v;
    __syncthreads();

    float denom = red[8] + red[9] + red[10] + red[11];
    if (t < C) {
        float pt = e / denom;
        p[t] = pt;
        mu_out[b * C + t] = pt;
    }
    __syncthreads();

    // ---- q (warps 0-3: one thread per row) and r (warps 4-7: one per col)
    if (t < C) {
        const int i  = t;
        const int sw = i & 31;
        const float* row = Ssm + i * C;
        float acc = 0.0f;
        #pragma unroll 8
        for (int k = 0; k < C; ++k)
            acc = fmaf(row[k ^ sw], p[k], acc);
        qv[i] = acc;
    } else {
        const int k = t - C;
        float acc = 0.0f;
        #pragma unroll 8
        for (int i2 = 0; i2 < C; ++i2)
            acc = fmaf(Ssm[i2 * C + (k ^ (i2 & 31))], p[i2], acc);
        rv[k] = acc;
    }
    __syncthreads();

    // ---- s = p . q
    float sv = (t < C) ? qv[t] * p[t] : 0.0f;
    #pragma unroll
    for (int o = 16; o > 0; o >>= 1)
        sv += __shfl_xor_sync(0xffffffffu, sv, o);
    if (t < C && (t & 31) == 0) red[t >> 5] = sv;
    __syncthreads();
    const float s = red[0] + red[1] + red[2] + red[3];

    // ---- output pass: out[i][k] = p_i p_k (S[i][k] - rv[k] - (qv[i] - s))
    #pragma unroll
    for (int j = 0; j < ELEMS_PER_THREAD; ++j) {
        int el = t + THREADS * j;
        int i  = el >> 7;
        int k  = el & (C - 1);
        float val = Ssm[i * C + (k ^ (i & 31))];
        Ob[el] = p[i] * p[k] * (val - rv[k] - (qv[i] - s));
    }
}

extern "C" void kernel_launch(void* const* d_in, const int* in_sizes, int n_in,
                              void* d_out, int out_size)
{
    // Identify inputs by size: Sigma is C times larger than mu.
    const float* in0 = (const float*)d_in[0];
    const float* in1 = (const float*)d_in[1];
    const float* mu;
    const float* Sigma;
    int B;
    if (in_sizes[0] <= in_sizes[1]) {
        mu = in0; Sigma = in1; B = in_sizes[0] / C;
    } else {
        mu = in1; Sigma = in0; B = in_sizes[1] / C;
    }

    float* mu_out  = (float*)d_out;               // first B*C elements
    float* sig_out = (float*)d_out + (size_t)B * C;

    const int smem = (C * C + 3 * C + 16) * sizeof(float);
    cudaFuncSetAttribute(softmax_sigma_kernel,
                         cudaFuncAttributeMaxDynamicSharedMemorySize, smem);
    softmax_sigma_kernel<<<B, THREADS, smem>>>(mu, Sigma, mu_out, sig_out);
}